// round 6
// baseline (speedup 1.0000x reference)
#include <cuda_runtime.h>
#include <math.h>

// CroquetGNN: 2-layer GCN, N=100000, E=3200000, feat 3 -> 16 -> 1
// out = sigmoid( GCNConv2( relu( GCNConv1(x) ) ) )
// GCNConv(x) = dinv[d] * segsum_{s->d}( dinv[s]*x[s] ) @ W (+ self loop + b)
//
// Multi-kernel + PDL: downstream kernels pre-launch, run an input-only
// preamble, then cudaGridDependencySynchronize() before touching upstream data.

#define MAXN 100000
#define MAXE 3200000
#define TBE 256   // edge kernels
#define TBN 128   // node kernels (latency-bound: more blocks -> better spread)

// ---- scratch (static device globals, BSS-zeroed at load; no allocation) ----
__device__ int2   g_edge[MAXE];    // converted pairs (int64 input path only)
__device__ int    g_deg[MAXN];     // in-degree   (reset to 0 in k_xd)
__device__ float  g_dinv[MAXN];    // rsqrt(deg+1)
__device__ float4 g_xd[MAXN];      // dinv[i] * x[i] (padded)
__device__ float4 g_xagg[MAXN];    // layer-1 agg (reset in k_node1)
__device__ float  g_gd[MAXN];      // dinv[i]*(relu(conv1).W2)
__device__ float  g_gagg[MAXN];    // layer-2 agg (reset in k_node2)

// per-block dtype detect from INPUT only: int64 LE with values < 2^31 has zero hi words
__device__ __forceinline__ int detect64_block(const int* __restrict__ idx) {
    __shared__ int s64;
    if (threadIdx.x < 32) {
        int hi = __ldg(&idx[2 * threadIdx.x + 1]);
        unsigned m = __ballot_sync(0xFFFFFFFFu, hi == 0);
        if (threadIdx.x == 0) s64 = (m == 0xFFFFFFFFu);
    }
    __syncthreads();
    return s64;
}

// ---- k_count: degree count (+ conversion to int2 on the int64 path) ----
__global__ void __launch_bounds__(TBE) k_count(const int* __restrict__ idx, int E) {
    cudaTriggerProgrammaticLaunchCompletion();   // no upstream: let k_xd pre-launch
    int is64 = detect64_block(idx);
    int e = blockIdx.x * TBE + threadIdx.x;
    if (e >= E) return;
    if (is64) {
        const long long* __restrict__ p = (const long long*)idx;
        int s = (int)__ldg(&p[e]);
        int d = (int)__ldg(&p[E + e]);
        g_edge[e] = make_int2(s, d);
        atomicAdd(&g_deg[d], 1);
    } else {
        int d = __ldg(&idx[E + e]);              // dst row only
        atomicAdd(&g_deg[d], 1);
    }
}

// ---- k_xd: dinv = rsqrt(deg+1); xd = dinv*x; reset deg ----
__global__ void __launch_bounds__(TBN) k_xd(const float* __restrict__ x, int N) {
    int i = blockIdx.x * TBN + threadIdx.x;
    float x0 = 0.f, x1 = 0.f, x2 = 0.f;
    if (i < N) { x0 = __ldg(&x[3 * i]); x1 = __ldg(&x[3 * i + 1]); x2 = __ldg(&x[3 * i + 2]); }
    cudaGridDependencySynchronize();             // wait k_count (deg complete)
    cudaTriggerProgrammaticLaunchCompletion();
    if (i >= N) return;
    int dg = g_deg[i];
    g_deg[i] = 0;                                // consumer reset (replay-safe)
    float di = rsqrtf((float)(dg + 1));          // +1 self loop
    g_dinv[i] = di;
    g_xd[i] = make_float4(x0 * di, x1 * di, x2 * di, 0.f);
}

// ---- k_edge1: xagg[d] += xd[s]  (one v4 RED per edge) ----
__global__ void __launch_bounds__(TBE) k_edge1(const int* __restrict__ idx, int E) {
    int is64 = detect64_block(idx);              // input-only preamble
    int e = blockIdx.x * TBE + threadIdx.x;
    int s = 0, d = 0;
    bool act = (e < E);
    if (act && !is64) { s = __ldg(&idx[e]); d = __ldg(&idx[E + e]); }
    cudaGridDependencySynchronize();             // wait k_xd (xd complete)
    cudaTriggerProgrammaticLaunchCompletion();
    if (!act) return;
    if (is64) { int2 ed = g_edge[e]; s = ed.x; d = ed.y; }
    float4 v = g_xd[s];
    float* dst = (float*)&g_xagg[d];
    asm volatile("red.global.add.v4.f32 [%0], {%1, %2, %3, %4};"
                 :: "l"(dst), "f"(v.x), "f"(v.y), "f"(v.z), "f"(v.w)
                 : "memory");
}

// ---- k_node1: finish conv1 (+self loop, dinv, b1), relu, .W2, scale dinv; reset xagg ----
__global__ void __launch_bounds__(TBN) k_node1(const float* __restrict__ W1,
                                               const float* __restrict__ b1,
                                               const float* __restrict__ W2, int N) {
    __shared__ float sW1[48], sb1[16], sW2[16];
    int t = threadIdx.x;
    if (t < 48) sW1[t] = __ldg(&W1[t]);          // input-only preamble
    if (t < 16) { sb1[t] = __ldg(&b1[t]); sW2[t] = __ldg(&W2[t]); }
    __syncthreads();
    cudaGridDependencySynchronize();             // wait k_edge1 (xagg complete)
    cudaTriggerProgrammaticLaunchCompletion();
    int i = blockIdx.x * TBN + t;
    if (i >= N) return;
    float di = g_dinv[i];
    float4 a = g_xagg[i];
    g_xagg[i] = make_float4(0.f, 0.f, 0.f, 0.f); // consumer reset
    float4 xd = g_xd[i];
    // self-loop contributes dinv[i]^2 * x[i] = dinv[i] * xd[i]
    float v0 = di * (a.x + xd.x);
    float v1 = di * (a.y + xd.y);
    float v2 = di * (a.z + xd.z);
    float g = 0.f;
#pragma unroll
    for (int c = 0; c < 16; c++) {
        float h = fmaf(v0, sW1[c], fmaf(v1, sW1[16 + c], fmaf(v2, sW1[32 + c], sb1[c])));
        h = fmaxf(h, 0.f);
        g = fmaf(h, sW2[c], g);
    }
    g_gd[i] = g * di;
}

// ---- k_edge2: gagg[d] += gd[s] ----
__global__ void __launch_bounds__(TBE) k_edge2(const int* __restrict__ idx, int E) {
    int is64 = detect64_block(idx);              // input-only preamble
    int e = blockIdx.x * TBE + threadIdx.x;
    int s = 0, d = 0;
    bool act = (e < E);
    if (act && !is64) { s = __ldg(&idx[e]); d = __ldg(&idx[E + e]); }
    cudaGridDependencySynchronize();             // wait k_node1 (gd complete)
    cudaTriggerProgrammaticLaunchCompletion();
    if (!act) return;
    if (is64) { int2 ed = g_edge[e]; s = ed.x; d = ed.y; }
    float v = g_gd[s];
    asm volatile("red.global.add.f32 [%0], %1;"
                 :: "l"(&g_gagg[d]), "f"(v) : "memory");
}

// ---- k_node2: finish conv2 (+self loop, dinv, b2, sigmoid); reset gagg ----
__global__ void __launch_bounds__(TBN) k_node2(const float* __restrict__ b2,
                                               float* __restrict__ out, int N) {
    float bias2 = __ldg(&b2[0]);                 // input-only preamble
    cudaGridDependencySynchronize();             // wait k_edge2 (gagg complete)
    int i = blockIdx.x * TBN + threadIdx.x;
    if (i >= N) return;
    float di = g_dinv[i];
    float ga = g_gagg[i];
    g_gagg[i] = 0.f;                             // consumer reset
    float s = di * (ga + g_gd[i]) + bias2;
    out[i] = 1.0f / (1.0f + expf(-s));
}

// ---- launch helper: cudaLaunchKernelExC with optional PDL attribute ----
static inline void launch1(const void* fn, int grid, int block, void** args, bool pdl) {
    cudaLaunchConfig_t cfg = {};
    cfg.gridDim = dim3((unsigned)grid, 1, 1);
    cfg.blockDim = dim3((unsigned)block, 1, 1);
    cfg.dynamicSmemBytes = 0;
    cfg.stream = 0;
    cudaLaunchAttribute attr;
    attr.id = cudaLaunchAttributeProgrammaticStreamSerialization;
    attr.val.programmaticStreamSerializationAllowed = 1;
    if (pdl) { cfg.attrs = &attr; cfg.numAttrs = 1; }
    cudaLaunchKernelExC(&cfg, fn, args);
}

extern "C" void kernel_launch(void* const* d_in, const int* in_sizes, int n_in,
                              void* d_out, int out_size) {
    const float* x   = (const float*)d_in[0];
    const int*   idx = (const int*)d_in[1];   // int32 or int64 (device-detected)
    const float* W1  = (const float*)d_in[2];
    const float* b1  = (const float*)d_in[3];
    const float* W2  = (const float*)d_in[4];
    const float* b2  = (const float*)d_in[5];
    float* out = (float*)d_out;

    int N_ = in_sizes[0] / 3;   // 100000
    int E_ = in_sizes[1] / 2;   // 3200000

    int nb_nn = (N_ + TBN - 1) / TBN;
    int nb_e  = (E_ + TBE - 1) / TBE;

    {   void* a[] = { (void*)&idx, (void*)&E_ };
        launch1((const void*)k_count, nb_e, TBE, a, false); }
    {   void* a[] = { (void*)&x, (void*)&N_ };
        launch1((const void*)k_xd, nb_nn, TBN, a, true); }
    {   void* a[] = { (void*)&idx, (void*)&E_ };
        launch1((const void*)k_edge1, nb_e, TBE, a, true); }
    {   void* a[] = { (void*)&W1, (void*)&b1, (void*)&W2, (void*)&N_ };
        launch1((const void*)k_node1, nb_nn, TBN, a, true); }
    {   void* a[] = { (void*)&idx, (void*)&E_ };
        launch1((const void*)k_edge2, nb_e, TBE, a, true); }
    {   void* a[] = { (void*)&b2, (void*)&out, (void*)&N_ };
        launch1((const void*)k_node2, nb_nn, TBN, a, true); }
}